// round 12
// baseline (speedup 1.0000x reference)
#include <cuda_runtime.h>
#include <cuda_bf16.h>
#include <math.h>

#define BB   512   // batch
#define TT   128   // time steps
#define FF   256   // features
#define HH   512   // hidden
#define KK   3     // fuzzy rules
#define NT   512   // threads in persistent rnn kernel

typedef unsigned long long ull;
typedef unsigned int uint;

// ------------------------------------------------------------------
// Device scratch
// ------------------------------------------------------------------
__device__ float g_xw[(size_t)TT * BB * HH];          // [T][B][H]
__device__ __nv_bfloat16 g_hh[2][(size_t)BB * HH];    // h hi (final state -> [0])
__device__ __nv_bfloat16 g_hl[2][(size_t)BB * HH];    // h lo
__device__ __nv_bfloat16 g_Whh[HH * HH];              // Wh hi  [k][n]
__device__ __nv_bfloat16 g_Whl[HH * HH];              // Wh lo
__device__ __nv_bfloat16 g_Wxh[FF * HH];              // (sigmoid(theta)*Wx) hi
__device__ __nv_bfloat16 g_Wxl[FF * HH];              // (sigmoid(theta)*Wx) lo
__device__ __nv_bfloat16 g_xh[(size_t)BB * TT * FF];  // x hi  [b*T+t][f]
__device__ __nv_bfloat16 g_xl[(size_t)BB * TT * FF];  // x lo
__device__ float g_gp[(HH / 2) * 20];                 // packed gate params / col-pair

// ------------------------------------------------------------------
// Helpers
// ------------------------------------------------------------------
__device__ __forceinline__ uint smem_u32(const void* p) {
    return (uint)__cvta_generic_to_shared(p);
}
__device__ __forceinline__ void ldmx4(uint* r, uint addr) {
    asm volatile("ldmatrix.sync.aligned.m8n8.x4.shared.b16 {%0,%1,%2,%3}, [%4];"
                 : "=r"(r[0]), "=r"(r[1]), "=r"(r[2]), "=r"(r[3]) : "r"(addr));
}
__device__ __forceinline__ void ldmx4t(uint* r, uint addr) {
    asm volatile("ldmatrix.sync.aligned.m8n8.x4.trans.shared.b16 {%0,%1,%2,%3}, [%4];"
                 : "=r"(r[0]), "=r"(r[1]), "=r"(r[2]), "=r"(r[3]) : "r"(addr));
}
__device__ __forceinline__ void mma16816(float* d, const uint* a, uint b0, uint b1) {
    asm volatile("mma.sync.aligned.m16n8k16.row.col.f32.bf16.bf16.f32 "
                 "{%0,%1,%2,%3}, {%4,%5,%6,%7}, {%8,%9}, {%0,%1,%2,%3};"
                 : "+f"(d[0]), "+f"(d[1]), "+f"(d[2]), "+f"(d[3])
                 : "r"(a[0]), "r"(a[1]), "r"(a[2]), "r"(a[3]), "r"(b0), "r"(b1));
}
__device__ __forceinline__ void cpasync16(uint saddr, const void* gaddr) {
    asm volatile("cp.async.cg.shared.global [%0], [%1], 16;"
                 :: "r"(saddr), "l"(gaddr));
}

// ------------------------------------------------------------------
// Prep: split Wh and Wxs into bf16 hi/lo, emit weights, gate params.
// ------------------------------------------------------------------
__global__ void prep_kernel(const float* __restrict__ theta,
                            const float* __restrict__ Wx,
                            const float* __restrict__ Wh,
                            const float* __restrict__ sigma,
                            const float* __restrict__ cC,
                            const float* __restrict__ qQ,
                            const float* __restrict__ bias,
                            float* __restrict__ out)
{
    int idx = blockIdx.x * blockDim.x + threadIdx.x;   // 262144 threads
    if (idx < HH * HH) {
        float w = Wh[idx];
        __nv_bfloat16 hi = __float2bfloat16_rn(w);
        g_Whh[idx] = hi;
        g_Whl[idx] = __float2bfloat16_rn(w - __bfloat162float(hi));
    }
    if (idx < FF * HH) {
        int f = idx >> 9;
        float w = (1.0f / (1.0f + expf(-theta[f]))) * Wx[idx];
        __nv_bfloat16 hi = __float2bfloat16_rn(w);
        g_Wxh[idx] = hi;
        g_Wxl[idx] = __float2bfloat16_rn(w - __bfloat162float(hi));
    }
    if (idx < FF) out[BB + idx] = 1.0f / (1.0f + expf(-theta[idx]));
    if (idx < HH / 2) {
        float* gp = g_gp + idx * 20;
        #pragma unroll
        for (int j = 0; j < 2; ++j) {
            int col = idx * 2 + j;
            float* o = gp + j * 10;
            #pragma unroll
            for (int s = 0; s < 3; ++s) {
                float sg = sigma[col * 3 + s];
                o[0 + s] = cC[col * 3 + s];
                o[4 + s] = 1.0f / (2.0f * sg * sg + 1e-8f);
                o[7 + s] = qQ[col * 3 + s];
            }
            o[3] = bias[col];
        }
    }
}

// ------------------------------------------------------------------
// x -> bf16 hi/lo split.
// ------------------------------------------------------------------
__global__ void __launch_bounds__(256) xcvt_kernel(const float* __restrict__ x)
{
    size_t i = ((size_t)blockIdx.x * 256 + threadIdx.x) * 4;
    float4 v = *(const float4*)(x + i);
    __nv_bfloat16 h0 = __float2bfloat16_rn(v.x);
    __nv_bfloat16 h1 = __float2bfloat16_rn(v.y);
    __nv_bfloat16 h2 = __float2bfloat16_rn(v.z);
    __nv_bfloat16 h3 = __float2bfloat16_rn(v.w);
    __nv_bfloat162 hv0; hv0.x = h0; hv0.y = h1;
    __nv_bfloat162 hv1; hv1.x = h2; hv1.y = h3;
    __nv_bfloat162 lv0;
    lv0.x = __float2bfloat16_rn(v.x - __bfloat162float(h0));
    lv0.y = __float2bfloat16_rn(v.y - __bfloat162float(h1));
    __nv_bfloat162 lv1;
    lv1.x = __float2bfloat16_rn(v.z - __bfloat162float(h2));
    lv1.y = __float2bfloat16_rn(v.w - __bfloat162float(h3));
    *(__nv_bfloat162*)(g_xh + i)     = hv0;
    *(__nv_bfloat162*)(g_xh + i + 2) = hv1;
    *(__nv_bfloat162*)(g_xl + i)     = lv0;
    *(__nv_bfloat162*)(g_xl + i + 2) = lv1;
}

// ------------------------------------------------------------------
// GEMM1 (HMMA hi/lo, proven): g_xw[t][b][h] = sum_f x[m][f] * Wxs[f][h]
// ------------------------------------------------------------------
#define SA1_PITCH 264
#define SB1_PITCH 136
#define SM1_AH 0
#define SM1_AL (64 * SA1_PITCH * 2)
#define SM1_BH (2 * 64 * SA1_PITCH * 2)
#define SM1_BL (SM1_BH + FF * SB1_PITCH * 2)
#define SMEM_G1_BYTES (SM1_BL + FF * SB1_PITCH * 2)

__global__ void __launch_bounds__(256, 1) gemm1_hmma()
{
    extern __shared__ char smem[];
    __nv_bfloat16* sAh = (__nv_bfloat16*)(smem + SM1_AH);
    __nv_bfloat16* sAl = (__nv_bfloat16*)(smem + SM1_AL);
    __nv_bfloat16* sBh = (__nv_bfloat16*)(smem + SM1_BH);
    __nv_bfloat16* sBl = (__nv_bfloat16*)(smem + SM1_BL);

    const int tid = threadIdx.x;
    const int m0  = blockIdx.x * 64;
    const int n0  = blockIdx.y * 128;

    {
        #pragma unroll
        for (int j = 0; j < 8; ++j) {
            int flat = tid + 256 * j;
            int row  = flat >> 5;
            int c8   = flat & 31;
            const size_t src = (size_t)(m0 + row) * FF + c8 * 8;
            *(uint4*)(sAh + row * SA1_PITCH + c8 * 8) = *(const uint4*)(g_xh + src);
            *(uint4*)(sAl + row * SA1_PITCH + c8 * 8) = *(const uint4*)(g_xl + src);
        }
    }
    {
        #pragma unroll
        for (int j = 0; j < 16; ++j) {
            int flat = tid + 256 * j;
            int row  = flat >> 4;
            int c8   = flat & 15;
            const size_t src = (size_t)row * HH + n0 + c8 * 8;
            *(uint4*)(sBh + row * SB1_PITCH + c8 * 8) = *(const uint4*)(g_Wxh + src);
            *(uint4*)(sBl + row * SB1_PITCH + c8 * 8) = *(const uint4*)(g_Wxl + src);
        }
    }
    __syncthreads();

    const int warp = tid >> 5;
    const int lane = tid & 31;
    const int mw   = warp & 1;
    const int nw   = warp >> 1;

    uint aAddrH[2], aAddrL[2];
    #pragma unroll
    for (int a = 0; a < 2; ++a) {
        int aRow = mw * 32 + a * 16 + (lane & 15);
        int aCol = (lane >> 4) * 8;
        aAddrH[a] = smem_u32(sAh + aRow * SA1_PITCH + aCol);
        aAddrL[a] = aAddrH[a] + (SM1_AL - SM1_AH);
    }
    uint bAddrH[2], bAddrL[2];
    #pragma unroll
    for (int bsub = 0; bsub < 2; ++bsub) {
        int bRow = lane & 15;
        int bCol = nw * 32 + bsub * 16 + (lane >> 4) * 8;
        bAddrH[bsub] = smem_u32(sBh + bRow * SB1_PITCH + bCol);
        bAddrL[bsub] = bAddrH[bsub] + (SM1_BL - SM1_BH);
    }

    float acc[2][4][4];
    #pragma unroll
    for (int a = 0; a < 2; ++a)
        #pragma unroll
        for (int j = 0; j < 4; ++j)
            #pragma unroll
            for (int r = 0; r < 4; ++r) acc[a][j][r] = 0.f;

    #pragma unroll 2
    for (int ks = 0; ks < 16; ++ks) {
        uint ah[2][4], al[2][4], bh[2][4], bl[2][4];
        #pragma unroll
        for (int a = 0; a < 2; ++a) {
            ldmx4(ah[a], aAddrH[a] + ks * 32);
            ldmx4(al[a], aAddrL[a] + ks * 32);
        }
        #pragma unroll
        for (int bsub = 0; bsub < 2; ++bsub) {
            ldmx4t(bh[bsub], bAddrH[bsub] + ks * (16 * SB1_PITCH * 2));
            ldmx4t(bl[bsub], bAddrL[bsub] + ks * (16 * SB1_PITCH * 2));
        }
        #pragma unroll
        for (int a = 0; a < 2; ++a) {
            #pragma unroll
            for (int bsub = 0; bsub < 2; ++bsub) {
                float* d0 = acc[a][bsub * 2 + 0];
                float* d1 = acc[a][bsub * 2 + 1];
                mma16816(d0, ah[a], bh[bsub][0], bh[bsub][1]);
                mma16816(d0, ah[a], bl[bsub][0], bl[bsub][1]);
                mma16816(d0, al[a], bh[bsub][0], bh[bsub][1]);
                mma16816(d1, ah[a], bh[bsub][2], bh[bsub][3]);
                mma16816(d1, ah[a], bl[bsub][2], bl[bsub][3]);
                mma16816(d1, al[a], bh[bsub][2], bh[bsub][3]);
            }
        }
    }

    #pragma unroll
    for (int a = 0; a < 2; ++a) {
        #pragma unroll
        for (int j = 0; j < 4; ++j) {
            const int col = n0 + nw * 32 + j * 8 + (lane & 3) * 2;
            #pragma unroll
            for (int p = 0; p < 2; ++p) {
                int rl = mw * 32 + a * 16 + (lane >> 2) + p * 8;
                int m  = m0 + rl;
                int t  = m & (TT - 1);
                int b  = m >> 7;
                float2 v = make_float2(acc[a][j][2 * p], acc[a][j][2 * p + 1]);
                *(float2*)&g_xw[((size_t)t * BB + b) * HH + col] = v;
            }
        }
    }
}

// ------------------------------------------------------------------
// Persistent recurrence kernel v3 — SELF-CONTAINED batch tiles.
// 32 CTAs x 512 threads. CTA = 16 batch rows x ALL 512 H columns.
// h (hi/lo bf16) lives in smem across all 128 steps; Wh hi/lo (1MB)
// streams from L2 per step in 16 double-buffered 64KB chunks (cp.async).
// 16 warps = 16 n32-slices; warp tile m16 x n32, full K per chunk.
// No cross-CTA communication at all.
//
// smem (bytes):
//   sAh   [16][520] bf16     @ 0       (16640)
//   sAl   [16][520] bf16     @ 16640   (16640)
//   B buffers (2): each { H: [32][520] bf16 (33280), L: +33280 }
//                            @ 33280, stride 66560  (133120)
//   sGP   5120 floats        @ 166400  (20480)
// total 186880
// ------------------------------------------------------------------
#define APITCH 520
#define RN_SAH 0
#define RN_SAL 16640
#define RN_SB  33280
#define RN_BUFSTRIDE 66560
#define RN_BL  33280          // lo offset within a buffer
#define RN_SGP 166400
#define SMEM_RNN_BYTES 186880

__global__ void __launch_bounds__(NT, 1) rnn_kernel()
{
    extern __shared__ char smem[];
    __nv_bfloat16* sAh = (__nv_bfloat16*)(smem + RN_SAH);
    __nv_bfloat16* sAl = (__nv_bfloat16*)(smem + RN_SAL);
    float*         sGP = (float*)(smem + RN_SGP);

    const int tid  = threadIdx.x;
    const int warp = tid >> 5;
    const int lane = tid & 31;
    const int m0   = blockIdx.x * 16;      // 32 CTAs x 16 batch rows

    const uint sbU    = smem_u32(smem + RN_SB);
    const uint aAddrH = smem_u32(smem) + ((lane & 15) * APITCH + (lane >> 4) * 8) * 2;
    const uint aAddrL = aAddrH + RN_SAL;
    const uint bLaneOff = ((lane & 15) * APITCH + warp * 32 + (lane >> 4) * 8) * 2;

    // ---- init: zero h (hi+lo regions incl padding), copy gate params ----
    {
        uint4 z4 = make_uint4(0u, 0u, 0u, 0u);
        for (int i = tid; i < (2 * 16640) / 16; i += NT)
            ((uint4*)smem)[i] = z4;
        for (int i = tid; i < 1280; i += NT)
            ((float4*)sGP)[i] = ((const float4*)g_gp)[i];
    }

    // ---- prologue: cp.async chunk 0 into buffer 0 ----
    {
        #pragma unroll
        for (int j = 0; j < 4; ++j) {
            int flat = tid + NT * j;       // < 2048
            int row  = flat >> 6;          // 0..31
            int c8   = flat & 63;
            uint d = sbU + row * (APITCH * 2) + c8 * 16;
            cpasync16(d,          g_Whh + (size_t)row * HH + c8 * 8);
            cpasync16(d + RN_BL,  g_Whl + (size_t)row * HH + c8 * 8);
        }
        asm volatile("cp.async.commit_group;" ::: "memory");
    }

    const int rl0 = lane >> 2;             // epilogue row base
    const int ec0 = (lane & 3) * 2;        // epilogue col offset within n8

    for (int t = 0; t < TT; ++t) {
        float acc[4][4];
        #pragma unroll
        for (int f = 0; f < 4; ++f)
            #pragma unroll
            for (int r = 0; r < 4; ++r) acc[f][r] = 0.f;

        #pragma unroll 1
        for (int c = 0; c < 16; ++c) {
            asm volatile("cp.async.wait_group 0;" ::: "memory");
            __syncthreads();

            // prefetch next chunk (wraps to chunk 0 for next step)
            if (!(t == TT - 1 && c == 15)) {
                const int  nc   = (c + 1) & 15;
                const uint dbuf = sbU + (uint)((c + 1) & 1) * RN_BUFSTRIDE;
                #pragma unroll
                for (int j = 0; j < 4; ++j) {
                    int flat = tid + NT * j;
                    int row  = flat >> 6;
                    int c8   = flat & 63;
                    uint d = dbuf + row * (APITCH * 2) + c8 * 16;
                    cpasync16(d,         g_Whh + (size_t)(nc * 32 + row) * HH + c8 * 8);
                    cpasync16(d + RN_BL, g_Whl + (size_t)(nc * 32 + row) * HH + c8 * 8);
                }
                asm volatile("cp.async.commit_group;" ::: "memory");
            }

            // compute chunk c
            const uint bufU = sbU + (uint)(c & 1) * RN_BUFSTRIDE;
            #pragma unroll
            for (int s = 0; s < 2; ++s) {
                const int kb = c * 32 + s * 16;
                uint ah[4], al[4];
                ldmx4(ah, aAddrH + kb * 2);
                ldmx4(al, aAddrL + kb * 2);
                #pragma unroll
                for (int nb = 0; nb < 2; ++nb) {
                    uint bh[4], bl[4];
                    uint baddr = bufU + bLaneOff + s * (16 * APITCH * 2) + nb * 32;
                    ldmx4t(bh, baddr);
                    ldmx4t(bl, baddr + RN_BL);
                    float* d0 = acc[nb * 2 + 0];
                    float* d1 = acc[nb * 2 + 1];
                    mma16816(d0, ah, bh[0], bh[1]);
                    mma16816(d0, ah, bl[0], bl[1]);
                    mma16816(d0, al, bh[0], bh[1]);
                    mma16816(d1, ah, bh[2], bh[3]);
                    mma16816(d1, ah, bl[2], bl[3]);
                    mma16816(d1, al, bh[2], bh[3]);
                }
            }
        }

        __syncthreads();   // all warps done reading sA for this step

        // ---- fused gate epilogue: 4 frags x 2 rows x 2 cols per thread ----
        const float* xwt = g_xw + (size_t)t * (BB * HH);
        #pragma unroll
        for (int f = 0; f < 4; ++f) {
            const int colg = warp * 32 + f * 8 + ec0;
            const float* gp = sGP + (colg >> 1) * 20;
            float4 p0 = *(const float4*)(gp + 0);
            float4 p1 = *(const float4*)(gp + 4);
            float4 p2 = *(const float4*)(gp + 8);
            float4 p3 = *(const float4*)(gp + 12);
            float4 p4 = *(const float4*)(gp + 16);
            float cc[2][3]  = {{p0.x, p0.y, p0.z}, {p2.z, p2.w, p3.x}};
            float bb2[2]    = {p0.w, p3.y};
            float iv[2][3]  = {{p1.x, p1.y, p1.z}, {p3.z, p3.w, p4.x}};
            float qq[2][3]  = {{p1.w, p2.x, p2.y}, {p4.y, p4.z, p4.w}};

            #pragma unroll
            for (int p = 0; p < 2; ++p) {
                const int rl = rl0 + p * 8;
                float2 xv = *(const float2*)&xwt[(size_t)(m0 + rl) * HH + colg];
                __nv_bfloat162 hhi = *(const __nv_bfloat162*)(sAh + rl * APITCH + colg);
                __nv_bfloat162 hlo = *(const __nv_bfloat162*)(sAl + rl * APITCH + colg);
                float hin[2] = {__low2float(hhi) + __low2float(hlo),
                                __high2float(hhi) + __high2float(hlo)};
                float zz[2] = {acc[f][2 * p + 0] + xv.x, acc[f][2 * p + 1] + xv.y};
                float xa[2] = {xv.x, xv.y};
                float hn[2];
                #pragma unroll
                for (int j = 0; j < 2; ++j) {
                    float z  = zz[j] + bb2[j];
                    float d0 = z - cc[j][0], d1 = z - cc[j][1], d2 = z - cc[j][2];
                    float mu0 = __expf(-d0 * d0 * iv[j][0]);
                    float mu1 = __expf(-d1 * d1 * iv[j][1]);
                    float mu2 = __expf(-d2 * d2 * iv[j][2]);
                    float num = mu0 * qq[j][0] + mu1 * qq[j][1] + mu2 * qq[j][2];
                    float den = mu0 + mu1 + mu2 + 1e-8f;
                    float g   = 1.0f / (1.0f + __expf(-__fdividef(num, den)));
                    float ex  = __expf(-2.0f * xa[j]);
                    float ni  = __fdividef(1.0f - ex, 1.0f + ex);
                    hn[j] = (1.0f - g) * hin[j] + g * ni;
                }
                __nv_bfloat16 h0i = __float2bfloat16_rn(hn[0]);
                __nv_bfloat16 h1i = __float2bfloat16_rn(hn[1]);
                __nv_bfloat162 hiv; hiv.x = h0i; hiv.y = h1i;
                __nv_bfloat162 lov;
                lov.x = __float2bfloat16_rn(hn[0] - __bfloat162float(h0i));
                lov.y = __float2bfloat16_rn(hn[1] - __bfloat162float(h1i));
                if (t < TT - 1) {
                    *(__nv_bfloat162*)(sAh + rl * APITCH + colg) = hiv;
                    *(__nv_bfloat162*)(sAl + rl * APITCH + colg) = lov;
                } else {
                    *(__nv_bfloat162*)&g_hh[0][(size_t)(m0 + rl) * HH + colg] = hiv;
                    *(__nv_bfloat162*)&g_hl[0][(size_t)(m0 + rl) * HH + colg] = lov;
                }
            }
        }
        __syncthreads();   // sA updates visible before next step's mainloop
    }
}

// ------------------------------------------------------------------
// Final: logits[b] = h_final[b] . Wc + bc
// ------------------------------------------------------------------
__global__ void __launch_bounds__(256) final_kernel(const float* __restrict__ Wc,
                                                    const float* __restrict__ bc,
                                                    float* __restrict__ out)
{
    const int warp = threadIdx.x >> 5;
    const int lane = threadIdx.x & 31;
    const int b = blockIdx.x * 8 + warp;
    const __nv_bfloat16* hhr = g_hh[0] + (size_t)b * HH;
    const __nv_bfloat16* hlr = g_hl[0] + (size_t)b * HH;
    float s = 0.0f;
    #pragma unroll
    for (int i = 0; i < 4; ++i) {
        int h = i * 128 + lane * 4;
        __nv_bfloat162 a0 = *(const __nv_bfloat162*)(hhr + h);
        __nv_bfloat162 a1 = *(const __nv_bfloat162*)(hhr + h + 2);
        __nv_bfloat162 l0 = *(const __nv_bfloat162*)(hlr + h);
        __nv_bfloat162 l1 = *(const __nv_bfloat162*)(hlr + h + 2);
        float4 w4 = *(const float4*)&Wc[h];
        s += (__low2float(a0)  + __low2float(l0))  * w4.x;
        s += (__high2float(a0) + __high2float(l0)) * w4.y;
        s += (__low2float(a1)  + __low2float(l1))  * w4.z;
        s += (__high2float(a1) + __high2float(l1)) * w4.w;
    }
    #pragma unroll
    for (int o = 16; o > 0; o >>= 1) s += __shfl_down_sync(0xffffffffu, s, o);
    if (lane == 0) out[b] = s + bc[0];
}

// ------------------------------------------------------------------
// Launch
// ------------------------------------------------------------------
extern "C" void kernel_launch(void* const* d_in, const int* in_sizes, int n_in,
                              void* d_out, int out_size)
{
    const float* x     = (const float*)d_in[0];
    const float* theta = (const float*)d_in[1];
    const float* Wx    = (const float*)d_in[2];
    const float* Wh    = (const float*)d_in[3];
    const float* bias  = (const float*)d_in[4];
    const float* c     = (const float*)d_in[5];
    const float* sigma = (const float*)d_in[6];
    const float* q     = (const float*)d_in[7];
    const float* Wc    = (const float*)d_in[8];
    const float* bc    = (const float*)d_in[9];
    float* out = (float*)d_out;

    static int configured = 0;
    if (!configured) {
        cudaFuncSetAttribute(rnn_kernel,
                             cudaFuncAttributeMaxDynamicSharedMemorySize,
                             SMEM_RNN_BYTES);
        cudaFuncSetAttribute(gemm1_hmma,
                             cudaFuncAttributeMaxDynamicSharedMemorySize,
                             SMEM_G1_BYTES);
        configured = 1;
    }

    prep_kernel<<<(HH * HH + 255) / 256, 256>>>(theta, Wx, Wh, sigma, c, q, bias, out);
    xcvt_kernel<<<(BB * TT * FF) / (256 * 4), 256>>>(x);
    gemm1_hmma<<<dim3((BB * TT) / 64, HH / 128), 256, SMEM_G1_BYTES>>>();
    rnn_kernel<<<32, NT, SMEM_RNN_BYTES>>>();
    final_kernel<<<64, 256>>>(Wc, bc, out);
}

// round 13
// speedup vs baseline: 2.2871x; 2.2871x over previous
#include <cuda_runtime.h>
#include <cuda_bf16.h>
#include <math.h>

#define BB   512   // batch
#define TT   128   // time steps
#define FF   256   // features
#define HH   512   // hidden
#define KK   3     // fuzzy rules

typedef unsigned long long ull;
typedef unsigned int uint;

// ------------------------------------------------------------------
// Device scratch
// ------------------------------------------------------------------
__device__ float g_xw[(size_t)TT * BB * HH];          // [T][B][H]
__device__ __nv_bfloat16 g_hh[2][(size_t)BB * HH];    // h hi, ping-pong [B][H]
__device__ __nv_bfloat16 g_hl[2][(size_t)BB * HH];    // h lo
__device__ __nv_bfloat16 g_Whh[HH * HH];              // Wh hi  [k][n]
__device__ __nv_bfloat16 g_Whl[HH * HH];              // Wh lo
__device__ __nv_bfloat16 g_Wxh[FF * HH];              // (sigmoid(theta)*Wx) hi
__device__ __nv_bfloat16 g_Wxl[FF * HH];              // (sigmoid(theta)*Wx) lo
__device__ __nv_bfloat16 g_xh[(size_t)BB * TT * FF];  // x hi  [b*T+t][f]
__device__ __nv_bfloat16 g_xl[(size_t)BB * TT * FF];  // x lo
__device__ float g_gp[(HH / 2) * 20];                 // packed gate params / col-pair

// ------------------------------------------------------------------
// Helpers
// ------------------------------------------------------------------
__device__ __forceinline__ uint smem_u32(const void* p) {
    return (uint)__cvta_generic_to_shared(p);
}
__device__ __forceinline__ void ldmx4(uint* r, uint addr) {
    asm volatile("ldmatrix.sync.aligned.m8n8.x4.shared.b16 {%0,%1,%2,%3}, [%4];"
                 : "=r"(r[0]), "=r"(r[1]), "=r"(r[2]), "=r"(r[3]) : "r"(addr));
}
__device__ __forceinline__ void ldmx4t(uint* r, uint addr) {
    asm volatile("ldmatrix.sync.aligned.m8n8.x4.trans.shared.b16 {%0,%1,%2,%3}, [%4];"
                 : "=r"(r[0]), "=r"(r[1]), "=r"(r[2]), "=r"(r[3]) : "r"(addr));
}
__device__ __forceinline__ void mma16816(float* d, const uint* a, uint b0, uint b1) {
    asm volatile("mma.sync.aligned.m16n8k16.row.col.f32.bf16.bf16.f32 "
                 "{%0,%1,%2,%3}, {%4,%5,%6,%7}, {%8,%9}, {%0,%1,%2,%3};"
                 : "+f"(d[0]), "+f"(d[1]), "+f"(d[2]), "+f"(d[3])
                 : "r"(a[0]), "r"(a[1]), "r"(a[2]), "r"(a[3]), "r"(b0), "r"(b1));
}
__device__ __forceinline__ void cpasync16(uint saddr, const void* gaddr) {
    asm volatile("cp.async.cg.shared.global [%0], [%1], 16;"
                 :: "r"(saddr), "l"(gaddr));
}

// ------------------------------------------------------------------
// Prep: zero h0, split Wh and Wxs into bf16 hi/lo, emit weights, gate params.
// ------------------------------------------------------------------
__global__ void prep_kernel(const float* __restrict__ theta,
                            const float* __restrict__ Wx,
                            const float* __restrict__ Wh,
                            const float* __restrict__ sigma,
                            const float* __restrict__ cC,
                            const float* __restrict__ qQ,
                            const float* __restrict__ bias,
                            float* __restrict__ out)
{
    int idx = blockIdx.x * blockDim.x + threadIdx.x;   // 262144 threads
    if (idx < BB * HH) {
        g_hh[0][idx] = __float2bfloat16_rn(0.0f);
        g_hl[0][idx] = __float2bfloat16_rn(0.0f);
    }
    if (idx < HH * HH) {
        float w = Wh[idx];
        __nv_bfloat16 hi = __float2bfloat16_rn(w);
        g_Whh[idx] = hi;
        g_Whl[idx] = __float2bfloat16_rn(w - __bfloat162float(hi));
    }
    if (idx < FF * HH) {
        int f = idx >> 9;
        float w = (1.0f / (1.0f + expf(-theta[f]))) * Wx[idx];
        __nv_bfloat16 hi = __float2bfloat16_rn(w);
        g_Wxh[idx] = hi;
        g_Wxl[idx] = __float2bfloat16_rn(w - __bfloat162float(hi));
    }
    if (idx < FF) out[BB + idx] = 1.0f / (1.0f + expf(-theta[idx]));
    if (idx < HH / 2) {
        float* gp = g_gp + idx * 20;
        #pragma unroll
        for (int j = 0; j < 2; ++j) {
            int col = idx * 2 + j;
            float* o = gp + j * 10;
            #pragma unroll
            for (int s = 0; s < 3; ++s) {
                float sg = sigma[col * 3 + s];
                o[0 + s] = cC[col * 3 + s];
                o[4 + s] = 1.0f / (2.0f * sg * sg + 1e-8f);
                o[7 + s] = qQ[col * 3 + s];
            }
            o[3] = bias[col];
        }
    }
}

// ------------------------------------------------------------------
// x -> bf16 hi/lo split.
// ------------------------------------------------------------------
__global__ void __launch_bounds__(256) xcvt_kernel(const float* __restrict__ x)
{
    size_t i = ((size_t)blockIdx.x * 256 + threadIdx.x) * 4;
    float4 v = *(const float4*)(x + i);
    __nv_bfloat16 h0 = __float2bfloat16_rn(v.x);
    __nv_bfloat16 h1 = __float2bfloat16_rn(v.y);
    __nv_bfloat16 h2 = __float2bfloat16_rn(v.z);
    __nv_bfloat16 h3 = __float2bfloat16_rn(v.w);
    __nv_bfloat162 hv0; hv0.x = h0; hv0.y = h1;
    __nv_bfloat162 hv1; hv1.x = h2; hv1.y = h3;
    __nv_bfloat162 lv0;
    lv0.x = __float2bfloat16_rn(v.x - __bfloat162float(h0));
    lv0.y = __float2bfloat16_rn(v.y - __bfloat162float(h1));
    __nv_bfloat162 lv1;
    lv1.x = __float2bfloat16_rn(v.z - __bfloat162float(h2));
    lv1.y = __float2bfloat16_rn(v.w - __bfloat162float(h3));
    *(__nv_bfloat162*)(g_xh + i)     = hv0;
    *(__nv_bfloat162*)(g_xh + i + 2) = hv1;
    *(__nv_bfloat162*)(g_xl + i)     = lv0;
    *(__nv_bfloat162*)(g_xl + i + 2) = lv1;
}

// ------------------------------------------------------------------
// GEMM1 (HMMA hi/lo, proven): g_xw[t][b][h] = sum_f x[m][f] * Wxs[f][h]
// ------------------------------------------------------------------
#define SA1_PITCH 264
#define SB1_PITCH 136
#define SM1_AH 0
#define SM1_AL (64 * SA1_PITCH * 2)
#define SM1_BH (2 * 64 * SA1_PITCH * 2)
#define SM1_BL (SM1_BH + FF * SB1_PITCH * 2)
#define SMEM_G1_BYTES (SM1_BL + FF * SB1_PITCH * 2)

__global__ void __launch_bounds__(256, 1) gemm1_hmma()
{
    extern __shared__ char smem[];
    __nv_bfloat16* sAh = (__nv_bfloat16*)(smem + SM1_AH);
    __nv_bfloat16* sAl = (__nv_bfloat16*)(smem + SM1_AL);
    __nv_bfloat16* sBh = (__nv_bfloat16*)(smem + SM1_BH);
    __nv_bfloat16* sBl = (__nv_bfloat16*)(smem + SM1_BL);

    const int tid = threadIdx.x;
    const int m0  = blockIdx.x * 64;
    const int n0  = blockIdx.y * 128;

    {
        #pragma unroll
        for (int j = 0; j < 8; ++j) {
            int flat = tid + 256 * j;
            int row  = flat >> 5;
            int c8   = flat & 31;
            const size_t src = (size_t)(m0 + row) * FF + c8 * 8;
            *(uint4*)(sAh + row * SA1_PITCH + c8 * 8) = *(const uint4*)(g_xh + src);
            *(uint4*)(sAl + row * SA1_PITCH + c8 * 8) = *(const uint4*)(g_xl + src);
        }
    }
    {
        #pragma unroll
        for (int j = 0; j < 16; ++j) {
            int flat = tid + 256 * j;
            int row  = flat >> 4;
            int c8   = flat & 15;
            const size_t src = (size_t)row * HH + n0 + c8 * 8;
            *(uint4*)(sBh + row * SB1_PITCH + c8 * 8) = *(const uint4*)(g_Wxh + src);
            *(uint4*)(sBl + row * SB1_PITCH + c8 * 8) = *(const uint4*)(g_Wxl + src);
        }
    }
    __syncthreads();

    const int warp = tid >> 5;
    const int lane = tid & 31;
    const int mw   = warp & 1;
    const int nw   = warp >> 1;

    uint aAddrH[2], aAddrL[2];
    #pragma unroll
    for (int a = 0; a < 2; ++a) {
        int aRow = mw * 32 + a * 16 + (lane & 15);
        int aCol = (lane >> 4) * 8;
        aAddrH[a] = smem_u32(sAh + aRow * SA1_PITCH + aCol);
        aAddrL[a] = aAddrH[a] + (SM1_AL - SM1_AH);
    }
    uint bAddrH[2], bAddrL[2];
    #pragma unroll
    for (int bsub = 0; bsub < 2; ++bsub) {
        int bRow = lane & 15;
        int bCol = nw * 32 + bsub * 16 + (lane >> 4) * 8;
        bAddrH[bsub] = smem_u32(sBh + bRow * SB1_PITCH + bCol);
        bAddrL[bsub] = bAddrH[bsub] + (SM1_BL - SM1_BH);
    }

    float acc[2][4][4];
    #pragma unroll
    for (int a = 0; a < 2; ++a)
        #pragma unroll
        for (int j = 0; j < 4; ++j)
            #pragma unroll
            for (int r = 0; r < 4; ++r) acc[a][j][r] = 0.f;

    #pragma unroll 2
    for (int ks = 0; ks < 16; ++ks) {
        uint ah[2][4], al[2][4], bh[2][4], bl[2][4];
        #pragma unroll
        for (int a = 0; a < 2; ++a) {
            ldmx4(ah[a], aAddrH[a] + ks * 32);
            ldmx4(al[a], aAddrL[a] + ks * 32);
        }
        #pragma unroll
        for (int bsub = 0; bsub < 2; ++bsub) {
            ldmx4t(bh[bsub], bAddrH[bsub] + ks * (16 * SB1_PITCH * 2));
            ldmx4t(bl[bsub], bAddrL[bsub] + ks * (16 * SB1_PITCH * 2));
        }
        #pragma unroll
        for (int a = 0; a < 2; ++a) {
            #pragma unroll
            for (int bsub = 0; bsub < 2; ++bsub) {
                float* d0 = acc[a][bsub * 2 + 0];
                float* d1 = acc[a][bsub * 2 + 1];
                mma16816(d0, ah[a], bh[bsub][0], bh[bsub][1]);
                mma16816(d0, ah[a], bl[bsub][0], bl[bsub][1]);
                mma16816(d0, al[a], bh[bsub][0], bh[bsub][1]);
                mma16816(d1, ah[a], bh[bsub][2], bh[bsub][3]);
                mma16816(d1, ah[a], bl[bsub][2], bl[bsub][3]);
                mma16816(d1, al[a], bh[bsub][2], bh[bsub][3]);
            }
        }
    }

    #pragma unroll
    for (int a = 0; a < 2; ++a) {
        #pragma unroll
        for (int j = 0; j < 4; ++j) {
            const int col = n0 + nw * 32 + j * 8 + (lane & 3) * 2;
            #pragma unroll
            for (int p = 0; p < 2; ++p) {
                int rl = mw * 32 + a * 16 + (lane >> 2) + p * 8;
                int m  = m0 + rl;
                int t  = m & (TT - 1);
                int b  = m >> 7;
                float2 v = make_float2(acc[a][j][2 * p], acc[a][j][2 * p + 1]);
                *(float2*)&g_xw[((size_t)t * BB + b) * HH + col] = v;
            }
        }
    }
}

// ------------------------------------------------------------------
// Step kernel v9: R10 structure + cp.async staging + early xw prefetch.
// CTA tile 32m x 64n, K=512, grid 16x8 = 128 CTAs, 256 threads.
// ------------------------------------------------------------------
#define SA_PITCH 520
#define SB_PITCH 72
#define SMEM_AH  0
#define SMEM_AL  (32 * SA_PITCH * 2)
#define SMEM_BH  (2 * 32 * SA_PITCH * 2)
#define SMEM_BL  (SMEM_BH + HH * SB_PITCH * 2)
#define SMEM_STEP_BYTES (SMEM_BL + HH * SB_PITCH * 2)

__global__ void __launch_bounds__(256, 1) step_kernel(int t)
{
    extern __shared__ char smem[];
    __nv_bfloat16* sAh = (__nv_bfloat16*)(smem + SMEM_AH);
    __nv_bfloat16* sAl = (__nv_bfloat16*)(smem + SMEM_AL);

    const int tid = threadIdx.x;
    const int m0  = blockIdx.x * 32;
    const int n0  = blockIdx.y * 64;

    const __nv_bfloat16* hh = g_hh[t & 1];
    const __nv_bfloat16* hl = g_hl[t & 1];

    const uint sAhU = smem_u32(smem + SMEM_AH);
    const uint sAlU = smem_u32(smem + SMEM_AL);
    const uint sBhU = smem_u32(smem + SMEM_BH);
    const uint sBlU = smem_u32(smem + SMEM_BL);

    // ---- stage A (h hi/lo) via cp.async ----
    {
        #pragma unroll
        for (int j = 0; j < 8; ++j) {
            int flat = tid + 256 * j;          // < 2048
            int row  = flat >> 6;              // 0..31
            int c8   = flat & 63;
            const size_t src = (size_t)(m0 + row) * HH + c8 * 8;
            cpasync16(sAhU + (row * SA_PITCH + c8 * 8) * 2, hh + src);
            cpasync16(sAlU + (row * SA_PITCH + c8 * 8) * 2, hl + src);
        }
    }
    // ---- stage B (Wh hi/lo slice) via cp.async ----
    {
        #pragma unroll
        for (int j = 0; j < 16; ++j) {
            int flat = tid + 256 * j;          // < 4096
            int row  = flat >> 3;              // 0..511
            int c8   = flat & 7;
            const size_t src = (size_t)row * HH + n0 + c8 * 8;
            cpasync16(sBhU + (row * SB_PITCH + c8 * 8) * 2, g_Whh + src);
            cpasync16(sBlU + (row * SB_PITCH + c8 * 8) * 2, g_Whl + src);
        }
    }
    asm volatile("cp.async.commit_group;" ::: "memory");

    const int warp = tid >> 5;
    const int lane = tid & 31;
    const int mw   = warp & 1;
    const int nw   = warp >> 1;
    const int rl0  = mw * 16 + (lane >> 2);
    const int c0   = (lane & 3) * 2;

    // ---- EARLY xw prefetch (DRAM-cold): issues while cp.async fills smem ----
    const float* xwt = g_xw + (size_t)t * (BB * HH);
    float2 xpre[2][2];
    #pragma unroll
    for (int half = 0; half < 2; ++half) {
        const int colg = n0 + nw * 16 + half * 8 + c0;
        #pragma unroll
        for (int p = 0; p < 2; ++p) {
            const int rg = m0 + rl0 + p * 8;
            xpre[half][p] = *(const float2*)&xwt[(size_t)rg * HH + colg];
        }
    }

    asm volatile("cp.async.wait_group 0;" ::: "memory");
    __syncthreads();

    // ---- HMMA mainloop ----
    const int aRow = mw * 16 + (lane & 15);
    const int aCol = (lane >> 4) * 8;
    uint aAddrH = sAhU + (aRow * SA_PITCH + aCol) * 2;
    uint aAddrL = aAddrH + (SMEM_AL - SMEM_AH);

    const int bRow = lane & 15;
    const int bCol = nw * 16 + (lane >> 4) * 8;
    uint bAddrH = sBhU + (bRow * SB_PITCH + bCol) * 2;
    uint bAddrL = bAddrH + (SMEM_BL - SMEM_BH);

    float acc0[4] = {0.f, 0.f, 0.f, 0.f};
    float acc1[4] = {0.f, 0.f, 0.f, 0.f};

    #pragma unroll 4
    for (int ks = 0; ks < 32; ++ks) {
        uint ah[4], al[4], bh[4], bl[4];
        ldmx4 (ah, aAddrH + ks * 32);
        ldmx4 (al, aAddrL + ks * 32);
        ldmx4t(bh, bAddrH + ks * (16 * SB_PITCH * 2));
        ldmx4t(bl, bAddrL + ks * (16 * SB_PITCH * 2));
        mma16816(acc0, ah, bh[0], bh[1]);
        mma16816(acc0, ah, bl[0], bl[1]);
        mma16816(acc0, al, bh[0], bh[1]);
        mma16816(acc1, ah, bh[2], bh[3]);
        mma16816(acc1, ah, bl[2], bl[3]);
        mma16816(acc1, al, bh[2], bh[3]);
    }

    // ---- fused gate epilogue ----
    __nv_bfloat16* hhn = g_hh[(t + 1) & 1];
    __nv_bfloat16* hln = g_hl[(t + 1) & 1];

    float* accs[2] = {acc0, acc1};
    #pragma unroll
    for (int half = 0; half < 2; ++half) {
        const float* d = accs[half];
        const int colg = n0 + nw * 16 + half * 8 + c0;

        const float* gp = g_gp + (size_t)(colg >> 1) * 20;
        float4 p0 = *(const float4*)(gp + 0);
        float4 p1 = *(const float4*)(gp + 4);
        float4 p2 = *(const float4*)(gp + 8);
        float4 p3 = *(const float4*)(gp + 12);
        float4 p4 = *(const float4*)(gp + 16);
        float cc[2][3]  = {{p0.x, p0.y, p0.z}, {p2.z, p2.w, p3.x}};
        float bb2[2]    = {p0.w, p3.y};
        float iv[2][3]  = {{p1.x, p1.y, p1.z}, {p3.z, p3.w, p4.x}};
        float qq[2][3]  = {{p1.w, p2.x, p2.y}, {p4.y, p4.z, p4.w}};

        #pragma unroll
        for (int p = 0; p < 2; ++p) {
            const int rl = rl0 + p * 8;
            const int rg = m0 + rl;
            float2 xv = xpre[half][p];
            __nv_bfloat162 hhi = *(const __nv_bfloat162*)(sAh + rl * SA_PITCH + colg);
            __nv_bfloat162 hlo = *(const __nv_bfloat162*)(sAl + rl * SA_PITCH + colg);
            float hin[2] = {__low2float(hhi) + __low2float(hlo),
                            __high2float(hhi) + __high2float(hlo)};
            float zz[2] = {d[2 * p + 0] + xv.x, d[2 * p + 1] + xv.y};
            float xa[2] = {xv.x, xv.y};
            float hn[2];
            #pragma unroll
            for (int j = 0; j < 2; ++j) {
                float z  = zz[j] + bb2[j];
                float d0 = z - cc[j][0], d1 = z - cc[j][1], d2 = z - cc[j][2];
                float mu0 = __expf(-d0 * d0 * iv[j][0]);
                float mu1 = __expf(-d1 * d1 * iv[j][1]);
                float mu2 = __expf(-d2 * d2 * iv[j][2]);
                float num = mu0 * qq[j][0] + mu1 * qq[j][1] + mu2 * qq[j][2];
                float den = mu0 + mu1 + mu2 + 1e-8f;
                float g   = 1.0f / (1.0f + __expf(-num / den));
                float ex  = __expf(-2.0f * xa[j]);
                float ni  = (1.0f - ex) / (1.0f + ex);
                hn[j] = (1.0f - g) * hin[j] + g * ni;
            }
            __nv_bfloat16 h0i = __float2bfloat16_rn(hn[0]);
            __nv_bfloat16 h1i = __float2bfloat16_rn(hn[1]);
            float l0 = hn[0] - __bfloat162float(h0i);
            float l1 = hn[1] - __bfloat162float(h1i);
            __nv_bfloat162 hiv; hiv.x = h0i; hiv.y = h1i;
            __nv_bfloat162 lov; lov.x = __float2bfloat16_rn(l0);
            lov.y = __float2bfloat16_rn(l1);
            *(__nv_bfloat162*)&hhn[(size_t)rg * HH + colg] = hiv;
            *(__nv_bfloat162*)&hln[(size_t)rg * HH + colg] = lov;
        }
    }
}

// ------------------------------------------------------------------
// Final: logits[b] = h_final[b] . Wc + bc
// ------------------------------------------------------------------
__global__ void __launch_bounds__(256) final_kernel(const float* __restrict__ Wc,
                                                    const float* __restrict__ bc,
                                                    float* __restrict__ out)
{
    const int warp = threadIdx.x >> 5;
    const int lane = threadIdx.x & 31;
    const int b = blockIdx.x * 8 + warp;
    const __nv_bfloat16* hhr = g_hh[0] + (size_t)b * HH;
    const __nv_bfloat16* hlr = g_hl[0] + (size_t)b * HH;
    float s = 0.0f;
    #pragma unroll
    for (int i = 0; i < 4; ++i) {
        int h = i * 128 + lane * 4;
        __nv_bfloat162 a0 = *(const __nv_bfloat162*)(hhr + h);
        __nv_bfloat162 a1 = *(const __nv_bfloat162*)(hhr + h + 2);
        __nv_bfloat162 l0 = *(const __nv_bfloat162*)(hlr + h);
        __nv_bfloat162 l1 = *(const __nv_bfloat162*)(hlr + h + 2);
        float4 w4 = *(const float4*)&Wc[h];
        s += (__low2float(a0)  + __low2float(l0))  * w4.x;
        s += (__high2float(a0) + __high2float(l0)) * w4.y;
        s += (__low2float(a1)  + __low2float(l1))  * w4.z;
        s += (__high2float(a1) + __high2float(l1)) * w4.w;
    }
    #pragma unroll
    for (int o = 16; o > 0; o >>= 1) s += __shfl_down_sync(0xffffffffu, s, o);
    if (lane == 0) out[b] = s + bc[0];
}

// ------------------------------------------------------------------
// Launch
// ------------------------------------------------------------------
extern "C" void kernel_launch(void* const* d_in, const int* in_sizes, int n_in,
                              void* d_out, int out_size)
{
    const float* x     = (const float*)d_in[0];
    const float* theta = (const float*)d_in[1];
    const float* Wx    = (const float*)d_in[2];
    const float* Wh    = (const float*)d_in[3];
    const float* bias  = (const float*)d_in[4];
    const float* c     = (const float*)d_in[5];
    const float* sigma = (const float*)d_in[6];
    const float* q     = (const float*)d_in[7];
    const float* Wc    = (const float*)d_in[8];
    const float* bc    = (const float*)d_in[9];
    float* out = (float*)d_out;

    static int configured = 0;
    if (!configured) {
        cudaFuncSetAttribute(step_kernel,
                             cudaFuncAttributeMaxDynamicSharedMemorySize,
                             SMEM_STEP_BYTES);
        cudaFuncSetAttribute(gemm1_hmma,
                             cudaFuncAttributeMaxDynamicSharedMemorySize,
                             SMEM_G1_BYTES);
        configured = 1;
    }

    prep_kernel<<<(BB * HH + 255) / 256, 256>>>(theta, Wx, Wh, sigma, c, q, bias, out);
    xcvt_kernel<<<(BB * TT * FF) / (256 * 4), 256>>>(x);
    gemm1_hmma<<<dim3((BB * TT) / 64, HH / 128), 256, SMEM_G1_BYTES>>>();
    for (int t = 0; t < TT; ++t)
        step_kernel<<<dim3(16, 8), 256, SMEM_STEP_BYTES>>>(t);
    final_kernel<<<64, 256>>>(Wc, bc, out);
}

// round 14
// speedup vs baseline: 2.7604x; 1.2070x over previous
#include <cuda_runtime.h>
#include <cuda_bf16.h>
#include <math.h>

#define BB   512   // batch
#define TT   128   // time steps
#define FF   256   // features
#define HH   512   // hidden
#define KK   3     // fuzzy rules

typedef unsigned long long ull;
typedef unsigned int uint;

// ------------------------------------------------------------------
// Device scratch
// ------------------------------------------------------------------
__device__ float g_xw[(size_t)TT * BB * HH];          // [T][B][H]
__device__ __nv_bfloat16 g_hh[2][(size_t)BB * HH];    // h hi, ping-pong [B][H]
__device__ __nv_bfloat16 g_hl[2][(size_t)BB * HH];    // h lo
__device__ __nv_bfloat16 g_Whh[HH * HH];              // Wh hi  [k][n]
__device__ __nv_bfloat16 g_Whl[HH * HH];              // Wh lo
__device__ __nv_bfloat16 g_Wxh[FF * HH];              // (sigmoid(theta)*Wx) hi
__device__ __nv_bfloat16 g_Wxl[FF * HH];              // (sigmoid(theta)*Wx) lo
__device__ __nv_bfloat16 g_xh[(size_t)BB * TT * FF];  // x hi  [b*T+t][f]
__device__ __nv_bfloat16 g_xl[(size_t)BB * TT * FF];  // x lo
__device__ float g_gp[(HH / 2) * 20];                 // packed gate params / col-pair

// ------------------------------------------------------------------
// Helpers
// ------------------------------------------------------------------
__device__ __forceinline__ uint smem_u32(const void* p) {
    return (uint)__cvta_generic_to_shared(p);
}
__device__ __forceinline__ void ldmx4(uint* r, uint addr) {
    asm volatile("ldmatrix.sync.aligned.m8n8.x4.shared.b16 {%0,%1,%2,%3}, [%4];"
                 : "=r"(r[0]), "=r"(r[1]), "=r"(r[2]), "=r"(r[3]) : "r"(addr));
}
__device__ __forceinline__ void ldmx4t(uint* r, uint addr) {
    asm volatile("ldmatrix.sync.aligned.m8n8.x4.trans.shared.b16 {%0,%1,%2,%3}, [%4];"
                 : "=r"(r[0]), "=r"(r[1]), "=r"(r[2]), "=r"(r[3]) : "r"(addr));
}
__device__ __forceinline__ void mma16816(float* d, const uint* a, uint b0, uint b1) {
    asm volatile("mma.sync.aligned.m16n8k16.row.col.f32.bf16.bf16.f32 "
                 "{%0,%1,%2,%3}, {%4,%5,%6,%7}, {%8,%9}, {%0,%1,%2,%3};"
                 : "+f"(d[0]), "+f"(d[1]), "+f"(d[2]), "+f"(d[3])
                 : "r"(a[0]), "r"(a[1]), "r"(a[2]), "r"(a[3]), "r"(b0), "r"(b1));
}
__device__ __forceinline__ void cpasync16(uint saddr, const void* gaddr) {
    asm volatile("cp.async.cg.shared.global [%0], [%1], 16;"
                 :: "r"(saddr), "l"(gaddr));
}

// ------------------------------------------------------------------
// Prep: zero h0, split Wh and Wxs into bf16 hi/lo, emit weights, gate params.
// ------------------------------------------------------------------
__global__ void prep_kernel(const float* __restrict__ theta,
                            const float* __restrict__ Wx,
                            const float* __restrict__ Wh,
                            const float* __restrict__ sigma,
                            const float* __restrict__ cC,
                            const float* __restrict__ qQ,
                            const float* __restrict__ bias,
                            float* __restrict__ out)
{
    int idx = blockIdx.x * blockDim.x + threadIdx.x;   // 262144 threads
    if (idx < BB * HH) {
        g_hh[0][idx] = __float2bfloat16_rn(0.0f);
        g_hl[0][idx] = __float2bfloat16_rn(0.0f);
    }
    if (idx < HH * HH) {
        float w = Wh[idx];
        __nv_bfloat16 hi = __float2bfloat16_rn(w);
        g_Whh[idx] = hi;
        g_Whl[idx] = __float2bfloat16_rn(w - __bfloat162float(hi));
    }
    if (idx < FF * HH) {
        int f = idx >> 9;
        float w = (1.0f / (1.0f + expf(-theta[f]))) * Wx[idx];
        __nv_bfloat16 hi = __float2bfloat16_rn(w);
        g_Wxh[idx] = hi;
        g_Wxl[idx] = __float2bfloat16_rn(w - __bfloat162float(hi));
    }
    if (idx < FF) out[BB + idx] = 1.0f / (1.0f + expf(-theta[idx]));
    if (idx < HH / 2) {
        float* gp = g_gp + idx * 20;
        #pragma unroll
        for (int j = 0; j < 2; ++j) {
            int col = idx * 2 + j;
            float* o = gp + j * 10;
            #pragma unroll
            for (int s = 0; s < 3; ++s) {
                float sg = sigma[col * 3 + s];
                o[0 + s] = cC[col * 3 + s];
                o[4 + s] = 1.0f / (2.0f * sg * sg + 1e-8f);
                o[7 + s] = qQ[col * 3 + s];
            }
            o[3] = bias[col];
        }
    }
}

// ------------------------------------------------------------------
// x -> bf16 hi/lo split.
// ------------------------------------------------------------------
__global__ void __launch_bounds__(256) xcvt_kernel(const float* __restrict__ x)
{
    size_t i = ((size_t)blockIdx.x * 256 + threadIdx.x) * 4;
    float4 v = *(const float4*)(x + i);
    __nv_bfloat16 h0 = __float2bfloat16_rn(v.x);
    __nv_bfloat16 h1 = __float2bfloat16_rn(v.y);
    __nv_bfloat16 h2 = __float2bfloat16_rn(v.z);
    __nv_bfloat16 h3 = __float2bfloat16_rn(v.w);
    __nv_bfloat162 hv0; hv0.x = h0; hv0.y = h1;
    __nv_bfloat162 hv1; hv1.x = h2; hv1.y = h3;
    __nv_bfloat162 lv0;
    lv0.x = __float2bfloat16_rn(v.x - __bfloat162float(h0));
    lv0.y = __float2bfloat16_rn(v.y - __bfloat162float(h1));
    __nv_bfloat162 lv1;
    lv1.x = __float2bfloat16_rn(v.z - __bfloat162float(h2));
    lv1.y = __float2bfloat16_rn(v.w - __bfloat162float(h3));
    *(__nv_bfloat162*)(g_xh + i)     = hv0;
    *(__nv_bfloat162*)(g_xh + i + 2) = hv1;
    *(__nv_bfloat162*)(g_xl + i)     = lv0;
    *(__nv_bfloat162*)(g_xl + i + 2) = lv1;
}

// ------------------------------------------------------------------
// GEMM1 (HMMA hi/lo, proven): g_xw[t][b][h] = sum_f x[m][f] * Wxs[f][h]
// ------------------------------------------------------------------
#define SA1_PITCH 264
#define SB1_PITCH 136
#define SM1_AH 0
#define SM1_AL (64 * SA1_PITCH * 2)
#define SM1_BH (2 * 64 * SA1_PITCH * 2)
#define SM1_BL (SM1_BH + FF * SB1_PITCH * 2)
#define SMEM_G1_BYTES (SM1_BL + FF * SB1_PITCH * 2)

__global__ void __launch_bounds__(256, 1) gemm1_hmma()
{
    extern __shared__ char smem[];
    __nv_bfloat16* sAh = (__nv_bfloat16*)(smem + SM1_AH);
    __nv_bfloat16* sAl = (__nv_bfloat16*)(smem + SM1_AL);
    __nv_bfloat16* sBh = (__nv_bfloat16*)(smem + SM1_BH);
    __nv_bfloat16* sBl = (__nv_bfloat16*)(smem + SM1_BL);

    const int tid = threadIdx.x;
    const int m0  = blockIdx.x * 64;
    const int n0  = blockIdx.y * 128;

    {
        #pragma unroll
        for (int j = 0; j < 8; ++j) {
            int flat = tid + 256 * j;
            int row  = flat >> 5;
            int c8   = flat & 31;
            const size_t src = (size_t)(m0 + row) * FF + c8 * 8;
            *(uint4*)(sAh + row * SA1_PITCH + c8 * 8) = *(const uint4*)(g_xh + src);
            *(uint4*)(sAl + row * SA1_PITCH + c8 * 8) = *(const uint4*)(g_xl + src);
        }
    }
    {
        #pragma unroll
        for (int j = 0; j < 16; ++j) {
            int flat = tid + 256 * j;
            int row  = flat >> 4;
            int c8   = flat & 15;
            const size_t src = (size_t)row * HH + n0 + c8 * 8;
            *(uint4*)(sBh + row * SB1_PITCH + c8 * 8) = *(const uint4*)(g_Wxh + src);
            *(uint4*)(sBl + row * SB1_PITCH + c8 * 8) = *(const uint4*)(g_Wxl + src);
        }
    }
    __syncthreads();

    const int warp = tid >> 5;
    const int lane = tid & 31;
    const int mw   = warp & 1;
    const int nw   = warp >> 1;

    uint aAddrH[2], aAddrL[2];
    #pragma unroll
    for (int a = 0; a < 2; ++a) {
        int aRow = mw * 32 + a * 16 + (lane & 15);
        int aCol = (lane >> 4) * 8;
        aAddrH[a] = smem_u32(sAh + aRow * SA1_PITCH + aCol);
        aAddrL[a] = aAddrH[a] + (SM1_AL - SM1_AH);
    }
    uint bAddrH[2], bAddrL[2];
    #pragma unroll
    for (int bsub = 0; bsub < 2; ++bsub) {
        int bRow = lane & 15;
        int bCol = nw * 32 + bsub * 16 + (lane >> 4) * 8;
        bAddrH[bsub] = smem_u32(sBh + bRow * SB1_PITCH + bCol);
        bAddrL[bsub] = bAddrH[bsub] + (SM1_BL - SM1_BH);
    }

    float acc[2][4][4];
    #pragma unroll
    for (int a = 0; a < 2; ++a)
        #pragma unroll
        for (int j = 0; j < 4; ++j)
            #pragma unroll
            for (int r = 0; r < 4; ++r) acc[a][j][r] = 0.f;

    #pragma unroll 2
    for (int ks = 0; ks < 16; ++ks) {
        uint ah[2][4], al[2][4], bh[2][4], bl[2][4];
        #pragma unroll
        for (int a = 0; a < 2; ++a) {
            ldmx4(ah[a], aAddrH[a] + ks * 32);
            ldmx4(al[a], aAddrL[a] + ks * 32);
        }
        #pragma unroll
        for (int bsub = 0; bsub < 2; ++bsub) {
            ldmx4t(bh[bsub], bAddrH[bsub] + ks * (16 * SB1_PITCH * 2));
            ldmx4t(bl[bsub], bAddrL[bsub] + ks * (16 * SB1_PITCH * 2));
        }
        #pragma unroll
        for (int a = 0; a < 2; ++a) {
            #pragma unroll
            for (int bsub = 0; bsub < 2; ++bsub) {
                float* d0 = acc[a][bsub * 2 + 0];
                float* d1 = acc[a][bsub * 2 + 1];
                mma16816(d0, ah[a], bh[bsub][0], bh[bsub][1]);
                mma16816(d0, ah[a], bl[bsub][0], bl[bsub][1]);
                mma16816(d0, al[a], bh[bsub][0], bh[bsub][1]);
                mma16816(d1, ah[a], bh[bsub][2], bh[bsub][3]);
                mma16816(d1, ah[a], bl[bsub][2], bl[bsub][3]);
                mma16816(d1, al[a], bh[bsub][2], bh[bsub][3]);
            }
        }
    }

    #pragma unroll
    for (int a = 0; a < 2; ++a) {
        #pragma unroll
        for (int j = 0; j < 4; ++j) {
            const int col = n0 + nw * 32 + j * 8 + (lane & 3) * 2;
            #pragma unroll
            for (int p = 0; p < 2; ++p) {
                int rl = mw * 32 + a * 16 + (lane >> 2) + p * 8;
                int m  = m0 + rl;
                int t  = m & (TT - 1);
                int b  = m >> 7;
                float2 v = make_float2(acc[a][j][2 * p], acc[a][j][2 * p + 1]);
                *(float2*)&g_xw[((size_t)t * BB + b) * HH + col] = v;
            }
        }
    }
}

// ------------------------------------------------------------------
// Step kernel v10: R13 + PDL. B (Wh) staged BEFORE the grid dependency
// sync (independent of predecessor); A (h) + xw after. Trigger fires
// right after the mainloop so the next step overlaps our epilogue.
// ------------------------------------------------------------------
#define SA_PITCH 520
#define SB_PITCH 72
#define SMEM_AH  0
#define SMEM_AL  (32 * SA_PITCH * 2)
#define SMEM_BH  (2 * 32 * SA_PITCH * 2)
#define SMEM_BL  (SMEM_BH + HH * SB_PITCH * 2)
#define SMEM_STEP_BYTES (SMEM_BL + HH * SB_PITCH * 2)

__global__ void __launch_bounds__(256, 1) step_kernel(int t)
{
    extern __shared__ char smem[];
    __nv_bfloat16* sAh = (__nv_bfloat16*)(smem + SMEM_AH);
    __nv_bfloat16* sAl = (__nv_bfloat16*)(smem + SMEM_AL);

    const int tid = threadIdx.x;
    const int m0  = blockIdx.x * 32;
    const int n0  = blockIdx.y * 64;

    const uint sAhU = smem_u32(smem + SMEM_AH);
    const uint sAlU = smem_u32(smem + SMEM_AL);
    const uint sBhU = smem_u32(smem + SMEM_BH);
    const uint sBlU = smem_u32(smem + SMEM_BL);

    // ---- stage B (Wh hi/lo slice) — independent of predecessor ----
    {
        #pragma unroll
        for (int j = 0; j < 16; ++j) {
            int flat = tid + 256 * j;          // < 4096
            int row  = flat >> 3;              // 0..511
            int c8   = flat & 7;
            const size_t src = (size_t)row * HH + n0 + c8 * 8;
            cpasync16(sBhU + (row * SB_PITCH + c8 * 8) * 2, g_Whh + src);
            cpasync16(sBlU + (row * SB_PITCH + c8 * 8) * 2, g_Whl + src);
        }
    }
    asm volatile("cp.async.commit_group;" ::: "memory");

    const int warp = tid >> 5;
    const int lane = tid & 31;
    const int mw   = warp & 1;
    const int nw   = warp >> 1;
    const int rl0  = mw * 16 + (lane >> 2);
    const int c0   = (lane & 3) * 2;

    // ---- gate params (written by prep, 2+ kernels back — safe pre-sync) ----
    float4 gpre[2][5];
    #pragma unroll
    for (int half = 0; half < 2; ++half) {
        const int colg = n0 + nw * 16 + half * 8 + c0;
        const float* gp = g_gp + (size_t)(colg >> 1) * 20;
        gpre[half][0] = *(const float4*)(gp + 0);
        gpre[half][1] = *(const float4*)(gp + 4);
        gpre[half][2] = *(const float4*)(gp + 8);
        gpre[half][3] = *(const float4*)(gp + 12);
        gpre[half][4] = *(const float4*)(gp + 16);
    }

    // ---- wait for predecessor's h / xw writes ----
    cudaGridDependencySynchronize();

    const __nv_bfloat16* hh = g_hh[t & 1];
    const __nv_bfloat16* hl = g_hl[t & 1];

    // ---- stage A (h hi/lo) via cp.async ----
    {
        #pragma unroll
        for (int j = 0; j < 8; ++j) {
            int flat = tid + 256 * j;          // < 2048
            int row  = flat >> 6;              // 0..31
            int c8   = flat & 63;
            const size_t src = (size_t)(m0 + row) * HH + c8 * 8;
            cpasync16(sAhU + (row * SA_PITCH + c8 * 8) * 2, hh + src);
            cpasync16(sAlU + (row * SA_PITCH + c8 * 8) * 2, hl + src);
        }
    }
    asm volatile("cp.async.commit_group;" ::: "memory");

    // ---- xw prefetch (DRAM-cold) overlaps the A staging wait ----
    const float* xwt = g_xw + (size_t)t * (BB * HH);
    float2 xpre[2][2];
    #pragma unroll
    for (int half = 0; half < 2; ++half) {
        const int colg = n0 + nw * 16 + half * 8 + c0;
        #pragma unroll
        for (int p = 0; p < 2; ++p) {
            const int rg = m0 + rl0 + p * 8;
            xpre[half][p] = *(const float2*)&xwt[(size_t)rg * HH + colg];
        }
    }

    asm volatile("cp.async.wait_group 0;" ::: "memory");
    __syncthreads();

    // ---- HMMA mainloop ----
    const int aRow = mw * 16 + (lane & 15);
    const int aCol = (lane >> 4) * 8;
    uint aAddrH = sAhU + (aRow * SA_PITCH + aCol) * 2;
    uint aAddrL = aAddrH + (SMEM_AL - SMEM_AH);

    const int bRow = lane & 15;
    const int bCol = nw * 16 + (lane >> 4) * 8;
    uint bAddrH = sBhU + (bRow * SB_PITCH + bCol) * 2;
    uint bAddrL = bAddrH + (SMEM_BL - SMEM_BH);

    float acc0[4] = {0.f, 0.f, 0.f, 0.f};
    float acc1[4] = {0.f, 0.f, 0.f, 0.f};

    #pragma unroll 4
    for (int ks = 0; ks < 32; ++ks) {
        uint ah[4], al[4], bh[4], bl[4];
        ldmx4 (ah, aAddrH + ks * 32);
        ldmx4 (al, aAddrL + ks * 32);
        ldmx4t(bh, bAddrH + ks * (16 * SB_PITCH * 2));
        ldmx4t(bl, bAddrL + ks * (16 * SB_PITCH * 2));
        mma16816(acc0, ah, bh[0], bh[1]);
        mma16816(acc0, ah, bl[0], bl[1]);
        mma16816(acc0, al, bh[0], bh[1]);
        mma16816(acc1, ah, bh[2], bh[3]);
        mma16816(acc1, ah, bl[2], bl[3]);
        mma16816(acc1, al, bh[2], bh[3]);
    }

    // ---- let the next step launch & stage its B while we finish ----
    cudaTriggerProgrammaticLaunchCompletion();

    // ---- fused gate epilogue ----
    __nv_bfloat16* hhn = g_hh[(t + 1) & 1];
    __nv_bfloat16* hln = g_hl[(t + 1) & 1];

    float* accs[2] = {acc0, acc1};
    #pragma unroll
    for (int half = 0; half < 2; ++half) {
        const float* d = accs[half];
        const int colg = n0 + nw * 16 + half * 8 + c0;

        float4 p0 = gpre[half][0];
        float4 p1 = gpre[half][1];
        float4 p2 = gpre[half][2];
        float4 p3 = gpre[half][3];
        float4 p4 = gpre[half][4];
        float cc[2][3]  = {{p0.x, p0.y, p0.z}, {p2.z, p2.w, p3.x}};
        float bb2[2]    = {p0.w, p3.y};
        float iv[2][3]  = {{p1.x, p1.y, p1.z}, {p3.z, p3.w, p4.x}};
        float qq[2][3]  = {{p1.w, p2.x, p2.y}, {p4.y, p4.z, p4.w}};

        #pragma unroll
        for (int p = 0; p < 2; ++p) {
            const int rl = rl0 + p * 8;
            const int rg = m0 + rl;
            float2 xv = xpre[half][p];
            __nv_bfloat162 hhi = *(const __nv_bfloat162*)(sAh + rl * SA_PITCH + colg);
            __nv_bfloat162 hlo = *(const __nv_bfloat162*)(sAl + rl * SA_PITCH + colg);
            float hin[2] = {__low2float(hhi) + __low2float(hlo),
                            __high2float(hhi) + __high2float(hlo)};
            float zz[2] = {d[2 * p + 0] + xv.x, d[2 * p + 1] + xv.y};
            float xa[2] = {xv.x, xv.y};
            float hn[2];
            #pragma unroll
            for (int j = 0; j < 2; ++j) {
                float z  = zz[j] + bb2[j];
                float d0 = z - cc[j][0], d1 = z - cc[j][1], d2 = z - cc[j][2];
                float mu0 = __expf(-d0 * d0 * iv[j][0]);
                float mu1 = __expf(-d1 * d1 * iv[j][1]);
                float mu2 = __expf(-d2 * d2 * iv[j][2]);
                float num = mu0 * qq[j][0] + mu1 * qq[j][1] + mu2 * qq[j][2];
                float den = mu0 + mu1 + mu2 + 1e-8f;
                float g   = 1.0f / (1.0f + __expf(-num / den));
                float ex  = __expf(-2.0f * xa[j]);
                float ni  = (1.0f - ex) / (1.0f + ex);
                hn[j] = (1.0f - g) * hin[j] + g * ni;
            }
            __nv_bfloat16 h0i = __float2bfloat16_rn(hn[0]);
            __nv_bfloat16 h1i = __float2bfloat16_rn(hn[1]);
            float l0 = hn[0] - __bfloat162float(h0i);
            float l1 = hn[1] - __bfloat162float(h1i);
            __nv_bfloat162 hiv; hiv.x = h0i; hiv.y = h1i;
            __nv_bfloat162 lov; lov.x = __float2bfloat16_rn(l0);
            lov.y = __float2bfloat16_rn(l1);
            *(__nv_bfloat162*)&hhn[(size_t)rg * HH + colg] = hiv;
            *(__nv_bfloat162*)&hln[(size_t)rg * HH + colg] = lov;
        }
    }
}

// ------------------------------------------------------------------
// Final: logits[b] = h_final[b] . Wc + bc
// ------------------------------------------------------------------
__global__ void __launch_bounds__(256) final_kernel(const float* __restrict__ Wc,
                                                    const float* __restrict__ bc,
                                                    float* __restrict__ out)
{
    const int warp = threadIdx.x >> 5;
    const int lane = threadIdx.x & 31;
    const int b = blockIdx.x * 8 + warp;
    const __nv_bfloat16* hhr = g_hh[0] + (size_t)b * HH;
    const __nv_bfloat16* hlr = g_hl[0] + (size_t)b * HH;
    float s = 0.0f;
    #pragma unroll
    for (int i = 0; i < 4; ++i) {
        int h = i * 128 + lane * 4;
        __nv_bfloat162 a0 = *(const __nv_bfloat162*)(hhr + h);
        __nv_bfloat162 a1 = *(const __nv_bfloat162*)(hhr + h + 2);
        __nv_bfloat162 l0 = *(const __nv_bfloat162*)(hlr + h);
        __nv_bfloat162 l1 = *(const __nv_bfloat162*)(hlr + h + 2);
        float4 w4 = *(const float4*)&Wc[h];
        s += (__low2float(a0)  + __low2float(l0))  * w4.x;
        s += (__high2float(a0) + __high2float(l0)) * w4.y;
        s += (__low2float(a1)  + __low2float(l1))  * w4.z;
        s += (__high2float(a1) + __high2float(l1)) * w4.w;
    }
    #pragma unroll
    for (int o = 16; o > 0; o >>= 1) s += __shfl_down_sync(0xffffffffu, s, o);
    if (lane == 0) out[b] = s + bc[0];
}

// ------------------------------------------------------------------
// Launch
// ------------------------------------------------------------------
extern "C" void kernel_launch(void* const* d_in, const int* in_sizes, int n_in,
                              void* d_out, int out_size)
{
    const float* x     = (const float*)d_in[0];
    const float* theta = (const float*)d_in[1];
    const float* Wx    = (const float*)d_in[2];
    const float* Wh    = (const float*)d_in[3];
    const float* bias  = (const float*)d_in[4];
    const float* c     = (const float*)d_in[5];
    const float* sigma = (const float*)d_in[6];
    const float* q     = (const float*)d_in[7];
    const float* Wc    = (const float*)d_in[8];
    const float* bc    = (const float*)d_in[9];
    float* out = (float*)d_out;

    static int configured = 0;
    if (!configured) {
        cudaFuncSetAttribute(step_kernel,
                             cudaFuncAttributeMaxDynamicSharedMemorySize,
                             SMEM_STEP_BYTES);
        cudaFuncSetAttribute(gemm1_hmma,
                             cudaFuncAttributeMaxDynamicSharedMemorySize,
                             SMEM_G1_BYTES);
        configured = 1;
    }

    prep_kernel<<<(BB * HH + 255) / 256, 256>>>(theta, Wx, Wh, sigma, c, q, bias, out);
    xcvt_kernel<<<(BB * TT * FF) / (256 * 4), 256>>>(x);
    gemm1_hmma<<<dim3((BB * TT) / 64, HH / 128), 256, SMEM_G1_BYTES>>>();

    // step kernels with programmatic dependent launch
    cudaLaunchConfig_t cfg = {};
    cfg.gridDim  = dim3(16, 8, 1);
    cfg.blockDim = dim3(256, 1, 1);
    cfg.dynamicSmemBytes = SMEM_STEP_BYTES;
    cudaLaunchAttribute attrs[1];
    attrs[0].id = cudaLaunchAttributeProgrammaticStreamSerialization;
    attrs[0].val.programmaticStreamSerializationAllowed = 1;
    cfg.attrs = attrs;
    cfg.numAttrs = 1;
    for (int t = 0; t < TT; ++t)
        cudaLaunchKernelEx(&cfg, step_kernel, t);

    final_kernel<<<64, 256>>>(Wc, bc, out);
}